// round 1
// baseline (speedup 1.0000x reference)
#include <cuda_runtime.h>

#define H_DIM 2048
#define B_DIM 4096
#define A_DIM 5
#define T_STEPS 10

// Scratch (device globals — no allocation allowed)
__device__ float g_Wc[H_DIM * H_DIM];     // W_in @ W_snn       (16 MB)
__device__ float g_rate[B_DIM * H_DIM];   // LIF firing rates   (32 MB)
__device__ float g_bp[H_DIM];             // b_in @ W_snn + b_snn

__device__ __forceinline__ float lif_rate(float c) {
    float v = 0.f;
    float cnt = 0.f;
#pragma unroll
    for (int t = 0; t < T_STEPS; t++) {
        v = v + (c - v) * 0.5f;          // tau = 2 (exact: /2 == *0.5)
        if (v >= 1.0f) { cnt += 1.0f; v = 0.0f; }  // spike + hard reset
    }
    return cnt * 0.1f;                    // mean over T_STEPS
}

// C[M,N] = A[M,K] @ B[K,N]; EPILOGUE=1: C = lif_rate(C + bias[col])
template <int EPILOGUE>
__global__ void __launch_bounds__(256, 2) sgemm_kernel(
    const float* __restrict__ Am, const float* __restrict__ Bm,
    float* __restrict__ Cm, const float* __restrict__ bias,
    int M, int N, int K)
{
    constexpr int BM = 128, BN = 128, BK = 16;
    __shared__ float As[BK][BM + 4];
    __shared__ float Bs[BK][BN + 4];

    const int tid = threadIdx.x;
    const int tx = tid & 15;       // N direction (x8)
    const int ty = tid >> 4;       // M direction (x8)
    const int bm = blockIdx.y * BM;
    const int bn = blockIdx.x * BN;

    float acc[8][8];
#pragma unroll
    for (int i = 0; i < 8; i++)
#pragma unroll
        for (int j = 0; j < 8; j++) acc[i][j] = 0.f;

    for (int k0 = 0; k0 < K; k0 += BK) {
        // Load A tile 128x16 (512 float4) and B tile 16x128 (512 float4)
#pragma unroll
        for (int i = 0; i < 2; i++) {
            int id = tid + i * 256;
            int ar = id >> 2;
            int ac = (id & 3) * 4;
            float4 av = *(const float4*)&Am[(size_t)(bm + ar) * K + k0 + ac];
            As[ac + 0][ar] = av.x;
            As[ac + 1][ar] = av.y;
            As[ac + 2][ar] = av.z;
            As[ac + 3][ar] = av.w;
            int br = id >> 5;
            int bc = (id & 31) * 4;
            float4 bv = *(const float4*)&Bm[(size_t)(k0 + br) * N + bn + bc];
            *(float4*)&Bs[br][bc] = bv;
        }
        __syncthreads();

#pragma unroll
        for (int k = 0; k < BK; k++) {
            float a[8], b[8];
            *(float4*)&a[0] = *(const float4*)&As[k][ty * 8];
            *(float4*)&a[4] = *(const float4*)&As[k][ty * 8 + 4];
            *(float4*)&b[0] = *(const float4*)&Bs[k][tx * 8];
            *(float4*)&b[4] = *(const float4*)&Bs[k][tx * 8 + 4];
#pragma unroll
            for (int i = 0; i < 8; i++)
#pragma unroll
                for (int j = 0; j < 8; j++)
                    acc[i][j] = fmaf(a[i], b[j], acc[i][j]);
        }
        __syncthreads();
    }

#pragma unroll
    for (int i = 0; i < 8; i++) {
        int row = bm + ty * 8 + i;
#pragma unroll
        for (int j = 0; j < 8; j++) {
            int col = bn + tx * 8 + j;
            float c = acc[i][j];
            if (EPILOGUE == 1) {
                c += bias[col];
                c = lif_rate(c);
            }
            Cm[(size_t)row * N + col] = c;
        }
    }
}

// g_bp = b_snn (init)
__global__ void bp_init_kernel(const float* __restrict__ b_snn) {
    int j = blockIdx.x * 256 + threadIdx.x;
    if (j < H_DIM) g_bp[j] = b_snn[j];
}

// g_bp[j] += sum_i b_in[i] * W_snn[i, j] (partial over 128 i's per block row)
__global__ void bp_acc_kernel(const float* __restrict__ b_in,
                              const float* __restrict__ W_snn) {
    int j = blockIdx.x * 256 + threadIdx.x;   // gridDim.x = 8
    int i0 = blockIdx.y * 128;                // gridDim.y = 16
    float acc = 0.f;
#pragma unroll 8
    for (int i = 0; i < 128; i++)
        acc = fmaf(b_in[i0 + i], W_snn[(size_t)(i0 + i) * H_DIM + j], acc);
    atomicAdd(&g_bp[j], acc);
}

// out[B,5] = ((rate @ W_out + b_out) * 0.5 - 1 >= 0) ? 1 : 0
__global__ void head_kernel(const float* __restrict__ rate,
                            const float* __restrict__ W_out,
                            const float* __restrict__ b_out,
                            float* __restrict__ out) {
    __shared__ float sW[H_DIM * A_DIM];   // 40 KB
    for (int i = threadIdx.x; i < H_DIM * A_DIM; i += blockDim.x)
        sW[i] = W_out[i];
    __syncthreads();

    int warp = threadIdx.x >> 5;
    int lane = threadIdx.x & 31;
    int row = blockIdx.x * 8 + warp;
    const float* r = rate + (size_t)row * H_DIM;

    float acc[A_DIM];
#pragma unroll
    for (int a = 0; a < A_DIM; a++) acc[a] = 0.f;

    for (int k = lane; k < H_DIM; k += 32) {
        float rv = r[k];
#pragma unroll
        for (int a = 0; a < A_DIM; a++)
            acc[a] = fmaf(rv, sW[k * A_DIM + a], acc[a]);
    }
#pragma unroll
    for (int a = 0; a < A_DIM; a++) {
#pragma unroll
        for (int off = 16; off; off >>= 1)
            acc[a] += __shfl_xor_sync(0xffffffffu, acc[a], off);
    }
    if (lane < A_DIM) {
        float pre = acc[lane] + b_out[lane];
        float v = pre * 0.5f;                       // single-step LIF from v=0
        out[(size_t)row * A_DIM + lane] = (v - 1.0f >= 0.f) ? 1.f : 0.f;
    }
}

extern "C" void kernel_launch(void* const* d_in, const int* in_sizes, int n_in,
                              void* d_out, int out_size) {
    const float* x     = (const float*)d_in[0];
    const float* W_in  = (const float*)d_in[1];
    const float* b_in  = (const float*)d_in[2];
    const float* W_snn = (const float*)d_in[3];
    const float* b_snn = (const float*)d_in[4];
    const float* W_out = (const float*)d_in[5];
    const float* b_out = (const float*)d_in[6];
    float* out = (float*)d_out;

    float *Wc, *rate, *bp;
    cudaGetSymbolAddress((void**)&Wc,   g_Wc);
    cudaGetSymbolAddress((void**)&rate, g_rate);
    cudaGetSymbolAddress((void**)&bp,   g_bp);

    // 1) W_c = W_in @ W_snn   (2048x2048x2048)
    {
        dim3 grid(H_DIM / 128, H_DIM / 128);
        sgemm_kernel<0><<<grid, 256>>>(W_in, W_snn, Wc, nullptr,
                                       H_DIM, H_DIM, H_DIM);
    }
    // 2) bp = b_in @ W_snn + b_snn
    bp_init_kernel<<<H_DIM / 256, 256>>>(b_snn);
    bp_acc_kernel<<<dim3(H_DIM / 256, 16), 256>>>(b_in, W_snn);
    // 3) rate = LIF(x @ W_c + bp)   (4096x2048x2048, fused LIF epilogue)
    {
        dim3 grid(H_DIM / 128, B_DIM / 128);
        sgemm_kernel<1><<<grid, 256>>>(x, Wc, rate, bp,
                                       B_DIM, H_DIM, H_DIM);
    }
    // 4) out = threshold(rate @ W_out + b_out)
    head_kernel<<<B_DIM / 8, 256>>>(rate, W_out, b_out, out);
}

// round 3
// speedup vs baseline: 5.3093x; 5.3093x over previous
#include <cuda_runtime.h>
#include <cuda_bf16.h>
#include <cstdint>

#define H_DIM 2048
#define B_DIM 4096
#define A_DIM 5
#define T_STEPS 10

// ---------------- device scratch (no allocation allowed) ----------------
__device__ __nv_bfloat16 g_xb[B_DIM * H_DIM];      // x in bf16            (16 MB)
__device__ __nv_bfloat16 g_Winb[H_DIM * H_DIM];    // W_in bf16            ( 8 MB)
__device__ __nv_bfloat16 g_WsnnT[H_DIM * H_DIM];   // W_snn^T bf16         ( 8 MB)
__device__ __nv_bfloat16 g_WcT[H_DIM * H_DIM];     // (W_in@W_snn)^T bf16  ( 8 MB)
__device__ float g_rate[B_DIM * H_DIM];            // LIF rates            (32 MB)
__device__ float g_bp[H_DIM];
__device__ float g_bp_part[16][H_DIM];

// ---------------- helpers ----------------
__device__ __forceinline__ uint32_t smem_u32(const void* p) {
    return (uint32_t)__cvta_generic_to_shared(p);
}
__device__ __forceinline__ void cp_async16(uint32_t dst, const void* src) {
    asm volatile("cp.async.cg.shared.global [%0], [%1], 16;" :: "r"(dst), "l"(src));
}
__device__ __forceinline__ void cp_commit() {
    asm volatile("cp.async.commit_group;");
}
template <int N>
__device__ __forceinline__ void cp_wait() {
    asm volatile("cp.async.wait_group %0;" :: "n"(N));
}
__device__ __forceinline__ void ldm_x4(uint32_t* r, uint32_t addr) {
    asm volatile("ldmatrix.sync.aligned.m8n8.x4.shared.b16 {%0,%1,%2,%3}, [%4];"
                 : "=r"(r[0]), "=r"(r[1]), "=r"(r[2]), "=r"(r[3]) : "r"(addr));
}
__device__ __forceinline__ void mma_bf16(float* c, const uint32_t* a, const uint32_t* b) {
    asm volatile(
        "mma.sync.aligned.m16n8k16.row.col.f32.bf16.bf16.f32 "
        "{%0,%1,%2,%3}, {%4,%5,%6,%7}, {%8,%9}, {%0,%1,%2,%3};"
        : "+f"(c[0]), "+f"(c[1]), "+f"(c[2]), "+f"(c[3])
        : "r"(a[0]), "r"(a[1]), "r"(a[2]), "r"(a[3]), "r"(b[0]), "r"(b[1]));
}

__device__ __forceinline__ float lif_rate(float c) {
    float v = 0.f, cnt = 0.f;
#pragma unroll
    for (int t = 0; t < T_STEPS; t++) {
        v = v + (c - v) * 0.5f;
        if (v >= 1.0f) { cnt += 1.0f; v = 0.0f; }
    }
    return cnt * 0.1f;
}

// ---------------- HMMA GEMM: D[M,N] = A[M,K] @ B[N,K]^T (bf16 in, f32 acc)
// EPI=0: store bf16.  EPI=1: store f32 lif_rate(D + bias[n]).
#define BK 32
#define SPAD 40   // padded bf16 row stride (80 B): conflict-free ldmatrix

template <int EPI>
__global__ void __launch_bounds__(256, 2) gemm_mma(
    const __nv_bfloat16* __restrict__ A, const __nv_bfloat16* __restrict__ B,
    void* __restrict__ Cv, const float* __restrict__ bias, int N, int K)
{
    __shared__ __nv_bfloat16 As[2][128][SPAD];
    __shared__ __nv_bfloat16 Bs[2][128][SPAD];

    const int tid = threadIdx.x;
    const int wid = tid >> 5;
    const int lane = tid & 31;
    const int bm = blockIdx.y * 128;
    const int bn = blockIdx.x * 128;
    const int wm = (wid >> 1) * 32;   // warp M offset within block
    const int wn = (wid & 1) * 64;    // warp N offset within block

    float acc[2][8][4];
#pragma unroll
    for (int mi = 0; mi < 2; mi++)
#pragma unroll
        for (int ni = 0; ni < 8; ni++)
#pragma unroll
            for (int j = 0; j < 4; j++) acc[mi][ni][j] = 0.f;

    auto stage = [&](int k0, int b) {
#pragma unroll
        for (int i = 0; i < 2; i++) {
            int id = tid + i * 256;           // 0..511
            int r = id >> 2, c = (id & 3) * 8;
            cp_async16(smem_u32(&As[b][r][c]), A + (size_t)(bm + r) * K + k0 + c);
            cp_async16(smem_u32(&Bs[b][r][c]), B + (size_t)(bn + r) * K + k0 + c);
        }
        cp_commit();
    };

    const int NS = K / BK;
    stage(0, 0);

    for (int s = 0; s < NS; s++) {
        if (s + 1 < NS) { stage((s + 1) * BK, (s + 1) & 1); cp_wait<1>(); }
        else            { cp_wait<0>(); }
        __syncthreads();
        const int b = s & 1;

#pragma unroll
        for (int ks = 0; ks < 2; ks++) {
            uint32_t af[2][4];
#pragma unroll
            for (int mi = 0; mi < 2; mi++)
                ldm_x4(af[mi], smem_u32(&As[b][wm + mi * 16 + (lane & 15)]
                                           [ks * 16 + (lane >> 4) * 8]));
            uint32_t bf[4][4];
#pragma unroll
            for (int np = 0; np < 4; np++) {
                // t0-7:(n0..7,k0) t8-15:(n0..7,k0+8) t16-23:(n8..15,k0) t24-31:(n8..15,k0+8)
                int rrow = wn + np * 16 + (lane & 7) + ((lane >> 4) << 3);
                int rcol = ks * 16 + (((lane >> 3) & 1) << 3);
                ldm_x4(bf[np], smem_u32(&Bs[b][rrow][rcol]));
            }
#pragma unroll
            for (int mi = 0; mi < 2; mi++)
#pragma unroll
                for (int ni = 0; ni < 8; ni++)
                    mma_bf16(acc[mi][ni], af[mi], &bf[ni >> 1][(ni & 1) * 2]);
        }
        __syncthreads();
    }

    // ---- epilogue straight from registers ----
    const int gr = lane >> 2;         // 0..7
    const int gc = (lane & 3) * 2;    // 0,2,4,6
#pragma unroll
    for (int mi = 0; mi < 2; mi++) {
#pragma unroll
        for (int ni = 0; ni < 8; ni++) {
            int col = bn + wn + ni * 8 + gc;
            int row0 = bm + wm + mi * 16 + gr;
            float c0 = acc[mi][ni][0], c1 = acc[mi][ni][1];
            float c2 = acc[mi][ni][2], c3 = acc[mi][ni][3];
            if (EPI == 1) {
                float b0 = bias[col], b1 = bias[col + 1];
                float2 lo = make_float2(lif_rate(c0 + b0), lif_rate(c1 + b1));
                float2 hi = make_float2(lif_rate(c2 + b0), lif_rate(c3 + b1));
                *(float2*)&((float*)Cv)[(size_t)row0 * N + col] = lo;
                *(float2*)&((float*)Cv)[(size_t)(row0 + 8) * N + col] = hi;
            } else {
                __nv_bfloat162 lo = __floats2bfloat162_rn(c0, c1);
                __nv_bfloat162 hi = __floats2bfloat162_rn(c2, c3);
                *(__nv_bfloat162*)&((__nv_bfloat16*)Cv)[(size_t)row0 * N + col] = lo;
                *(__nv_bfloat162*)&((__nv_bfloat16*)Cv)[(size_t)(row0 + 8) * N + col] = hi;
            }
        }
    }
}

// ---------------- conversion kernels ----------------
__global__ void conv_bf16_kernel(const float4* __restrict__ in, uint2* __restrict__ out, int n4) {
    int i = blockIdx.x * 256 + threadIdx.x;
    if (i < n4) {
        float4 v = in[i];
        __nv_bfloat162 lo = __floats2bfloat162_rn(v.x, v.y);
        __nv_bfloat162 hi = __floats2bfloat162_rn(v.z, v.w);
        uint2 o;
        o.x = *reinterpret_cast<unsigned int*>(&lo);
        o.y = *reinterpret_cast<unsigned int*>(&hi);
        out[i] = o;
    }
}

// out[j, m] = bf16(in[m, j])   (2048 x 2048)
__global__ void convT_bf16_kernel(const float* __restrict__ in, __nv_bfloat16* __restrict__ out) {
    __shared__ float t[32][33];
    int j0 = blockIdx.x * 32, m0 = blockIdx.y * 32;
    int tx = threadIdx.x, ty = threadIdx.y;   // 32 x 8
#pragma unroll
    for (int i = 0; i < 4; i++)
        t[ty + i * 8][tx] = in[(size_t)(m0 + ty + i * 8) * H_DIM + j0 + tx];
    __syncthreads();
#pragma unroll
    for (int i = 0; i < 4; i++)
        out[(size_t)(j0 + ty + i * 8) * H_DIM + m0 + tx] = __float2bfloat16(t[tx][ty + i * 8]);
}

// ---------------- bias path: bp = b_in @ W_snn + b_snn (deterministic) ----------------
__global__ void bp_part_kernel(const float* __restrict__ b_in, const float* __restrict__ W_snn) {
    int j = blockIdx.x * 256 + threadIdx.x;   // gridDim.x = 8
    int p = blockIdx.y;                       // gridDim.y = 16
    int i0 = p * 128;
    float acc = 0.f;
#pragma unroll 8
    for (int i = 0; i < 128; i++)
        acc = fmaf(b_in[i0 + i], W_snn[(size_t)(i0 + i) * H_DIM + j], acc);
    g_bp_part[p][j] = acc;
}
__global__ void bp_reduce_kernel(const float* __restrict__ b_snn) {
    int j = blockIdx.x * 256 + threadIdx.x;
    float acc = b_snn[j];
#pragma unroll
    for (int p = 0; p < 16; p++) acc += g_bp_part[p][j];
    g_bp[j] = acc;
}

// ---------------- output head ----------------
__global__ void head_kernel(const float* __restrict__ rate,
                            const float* __restrict__ W_out,
                            const float* __restrict__ b_out,
                            float* __restrict__ out) {
    __shared__ float sW[H_DIM * A_DIM];
    for (int i = threadIdx.x; i < H_DIM * A_DIM; i += blockDim.x)
        sW[i] = W_out[i];
    __syncthreads();

    int warp = threadIdx.x >> 5;
    int lane = threadIdx.x & 31;
    int row = blockIdx.x * 8 + warp;
    const float* r = rate + (size_t)row * H_DIM;

    float acc[A_DIM];
#pragma unroll
    for (int a = 0; a < A_DIM; a++) acc[a] = 0.f;
    for (int k = lane; k < H_DIM; k += 32) {
        float rv = r[k];
#pragma unroll
        for (int a = 0; a < A_DIM; a++)
            acc[a] = fmaf(rv, sW[k * A_DIM + a], acc[a]);
    }
#pragma unroll
    for (int a = 0; a < A_DIM; a++) {
#pragma unroll
        for (int off = 16; off; off >>= 1)
            acc[a] += __shfl_xor_sync(0xffffffffu, acc[a], off);
    }
    if (lane < A_DIM) {
        float pre = acc[lane] + b_out[lane];
        float v = pre * 0.5f;
        out[(size_t)row * A_DIM + lane] = (v - 1.0f >= 0.f) ? 1.f : 0.f;
    }
}

// ---------------- launch ----------------
extern "C" void kernel_launch(void* const* d_in, const int* in_sizes, int n_in,
                              void* d_out, int out_size) {
    const float* x     = (const float*)d_in[0];
    const float* W_in  = (const float*)d_in[1];
    const float* b_in  = (const float*)d_in[2];
    const float* W_snn = (const float*)d_in[3];
    const float* b_snn = (const float*)d_in[4];
    const float* W_out = (const float*)d_in[5];
    const float* b_out = (const float*)d_in[6];
    float* out = (float*)d_out;

    __nv_bfloat16 *xb, *Winb, *WsnnT, *WcT;
    float *rate, *bp;
    cudaGetSymbolAddress((void**)&xb,    g_xb);
    cudaGetSymbolAddress((void**)&Winb,  g_Winb);
    cudaGetSymbolAddress((void**)&WsnnT, g_WsnnT);
    cudaGetSymbolAddress((void**)&WcT,   g_WcT);
    cudaGetSymbolAddress((void**)&rate,  g_rate);
    cudaGetSymbolAddress((void**)&bp,    g_bp);

    // conversions
    conv_bf16_kernel<<<(B_DIM * H_DIM / 4 + 255) / 256, 256>>>((const float4*)x, (uint2*)xb,
                                                               B_DIM * H_DIM / 4);
    conv_bf16_kernel<<<(H_DIM * H_DIM / 4 + 255) / 256, 256>>>((const float4*)W_in, (uint2*)Winb,
                                                               H_DIM * H_DIM / 4);
    convT_bf16_kernel<<<dim3(H_DIM / 32, H_DIM / 32), dim3(32, 8)>>>(W_snn, WsnnT);

    // bias path
    bp_part_kernel<<<dim3(H_DIM / 256, 16), 256>>>(b_in, W_snn);
    bp_reduce_kernel<<<H_DIM / 256, 256>>>(b_snn);

    // GEMM1: WcT[j,i] = sum_m WsnnT[j,m] * Winb[i,m]   (bf16 out)
    gemm_mma<0><<<dim3(H_DIM / 128, H_DIM / 128), 256>>>(
        WsnnT, Winb, (void*)WcT, nullptr, H_DIM, H_DIM);

    // GEMM2: rate[b,n] = lif(sum_k xb[b,k] * WcT[n,k] + bp[n])   (f32 out)
    gemm_mma<1><<<dim3(H_DIM / 128, B_DIM / 128), 256>>>(
        xb, WcT, (void*)rate, bp, H_DIM, H_DIM);

    // head
    head_kernel<<<B_DIM / 8, 256>>>(rate, W_out, b_out, out);
}